// round 1
// baseline (speedup 1.0000x reference)
#include <cuda_runtime.h>
#include <math.h>

#define NN 1024
#define CC 64
#define NITERS 20
#define LSCALE 0.001f

// Scratch in __device__ globals (allocation rules forbid cudaMalloc)
__device__ float g_ps[NN*CC];
__device__ float g_pt[NN*CC];
__device__ float g_W [NN*NN];
__device__ float g_Km[NN*NN];
__device__ float g_KT[NN*NN];
__device__ float g_u [NN];   // stored as reciprocal row scaling u = 1/(K v)
__device__ float g_v [NN];   // stored as reciprocal col scaling v = 1/(K^T u)
__device__ float g_partial[256];

__device__ __forceinline__ float warp_sum(float v) {
#pragma unroll
    for (int o = 16; o > 0; o >>= 1) v += __shfl_down_sync(0xffffffffu, v, o);
    return v;
}
__device__ __forceinline__ float warp_max(float v) {
#pragma unroll
    for (int o = 16; o > 0; o >>= 1) v = fmaxf(v, __shfl_down_sync(0xffffffffu, v, o));
    return v;
}

// 256-thread block sum, result broadcast to all threads. Deterministic tree.
__device__ float block_sum256(float v) {
    __shared__ float s[8];
    __shared__ float total;
    int t = threadIdx.x;
    v = warp_sum(v);
    if ((t & 31) == 0) s[t >> 5] = v;
    __syncthreads();
    if (t == 0) {
        float r = 0.f;
#pragma unroll
        for (int i = 0; i < 8; i++) r += s[i];
        total = r;
    }
    __syncthreads();
    return total;
}

__device__ float block_max256(float v) {
    __shared__ float s[8];
    __shared__ float total;
    int t = threadIdx.x;
    v = warp_max(v);
    if ((t & 31) == 0) s[t >> 5] = v;
    __syncthreads();
    if (t == 0) {
        float r = -3.4e38f;
#pragma unroll
        for (int i = 0; i < 8; i++) r = fmaxf(r, s[i]);
        total = r;
    }
    __syncthreads();
    return total;
}

// Softmax over the N axis for batch sample 7 only (the only one that matters).
// grid: (64 channels, 2 tensors), block: 256 threads, 4 rows each.
__global__ void softmax_kernel(const float* __restrict__ ys,
                               const float* __restrict__ yt) {
    int c = blockIdx.x;
    const float* y = (blockIdx.y == 0) ? ys : yt;
    float* p       = (blockIdx.y == 0) ? g_ps : g_pt;
    const float* base = y + 7 * NN * CC;
    int t = threadIdx.x;

    float vals[4];
    float mx = -3.4e38f;
#pragma unroll
    for (int k = 0; k < 4; k++) {
        vals[k] = base[(t + k * 256) * CC + c] * 0.5f;   // y / T, T=2
        mx = fmaxf(mx, vals[k]);
    }
    mx = block_max256(mx);

    float s = 0.f;
#pragma unroll
    for (int k = 0; k < 4; k++) { vals[k] = expf(vals[k] - mx); s += vals[k]; }
    s = block_sum256(s);

    float inv = 1.0f / s;
#pragma unroll
    for (int k = 0; k < 4; k++) p[(t + k * 256) * CC + c] = vals[k] * inv;
}

// W[i,j] = sum_c |ps[i,c] - pt[j,c]|;  K = exp(-W/0.1);  also writes K^T.
// 64x64 tile per block, 256 threads, 4x4 micro-tile per thread.
__global__ void wk_kernel() {
    __shared__ float4 sA[64 * 17];  // padded rows: 17 float4 per 64-ch row
    __shared__ float4 sB[64 * 17];
    int t = threadIdx.x;
    int bi = blockIdx.y, bj = blockIdx.x;
    const float4* A = (const float4*)g_ps;
    const float4* B = (const float4*)g_pt;

#pragma unroll
    for (int k = 0; k < 4; k++) {
        int idx = t + k * 256;           // 1024 float4 slots (64 rows x 16)
        int r = idx >> 4, c4 = idx & 15;
        sA[r * 17 + c4] = A[(bi * 64 + r) * 16 + c4];
        sB[r * 17 + c4] = B[(bj * 64 + r) * 16 + c4];
    }
    __syncthreads();

    int tx = t & 15, ty = t >> 4;
    float acc[4][4];
#pragma unroll
    for (int r = 0; r < 4; r++)
#pragma unroll
        for (int q = 0; q < 4; q++) acc[r][q] = 0.f;

#pragma unroll
    for (int c4 = 0; c4 < 16; c4++) {
        float4 a[4], b[4];
#pragma unroll
        for (int r = 0; r < 4; r++) a[r] = sA[(ty * 4 + r) * 17 + c4];
#pragma unroll
        for (int q = 0; q < 4; q++) b[q] = sB[(tx * 4 + q) * 17 + c4];
#pragma unroll
        for (int r = 0; r < 4; r++)
#pragma unroll
            for (int q = 0; q < 4; q++)
                acc[r][q] += fabsf(a[r].x - b[q].x) + fabsf(a[r].y - b[q].y)
                           + fabsf(a[r].z - b[q].z) + fabsf(a[r].w - b[q].w);
    }
    __syncthreads();

    float* strans = (float*)sA;  // reuse sA region: 4096 floats = 16KB <= 17.4KB
#pragma unroll
    for (int r = 0; r < 4; r++) {
        int gi = bi * 64 + ty * 4 + r;
#pragma unroll
        for (int q = 0; q < 4; q++) {
            int gj = bj * 64 + tx * 4 + q;
            float w  = acc[r][q];
            float kk = expf(-10.0f * w);             // exp(-W/eps), eps=0.1
            g_W [gi * NN + gj] = w;
            g_Km[gi * NN + gj] = kk;
            strans[(tx * 4 + q) * 64 + (ty * 4 + r)] = kk;
        }
    }
    __syncthreads();
#pragma unroll
    for (int k = 0; k < 16; k++) {
        int idx = t + k * 256;
        int lr = idx >> 6, lc = idx & 63;
        g_KT[(bj * 64 + lr) * NN + bi * 64 + lc] = strans[idx];
    }
}

__global__ void init_kernel() {
    int i = blockIdx.x * 256 + threadIdx.x;
    if (i < NN) g_v[i] = 1.0f;
}

// Sinkhorn half-step: dir=0: u = 1/(K  . v)    dir=1: v = 1/(K^T . u)
// One block per row, 256 threads, one float4 per thread.
__global__ void matvec_kernel(int dir) {
    const float* M   = dir ? g_KT : g_Km;
    const float* vin = dir ? g_u  : g_v;
    float*       vout = dir ? g_v : g_u;

    int row = blockIdx.x;
    int t = threadIdx.x;
    const float4* Mr = (const float4*)(M + row * NN);
    const float4* V  = (const float4*)vin;
    float4 m = Mr[t], v = V[t];
    float s = m.x * v.x + m.y * v.y + m.z * v.z + m.w * v.w;
    s = block_sum256(s);
    if (t == 0) vout[row] = 1.0f / s;
}

// loss partials: sum_ij u_i * K_ij * v_j * W_ij over 4 rows per block
__global__ void loss_partial_kernel() {
    int t = threadIdx.x, b = blockIdx.x;
    const float4* Vv = (const float4*)g_v;
    float4 vv = Vv[t];
    float s = 0.f;
#pragma unroll
    for (int r = 0; r < 4; r++) {
        int row = b * 4 + r;
        float ur = g_u[row];
        const float4* Wr = (const float4*)(g_W  + row * NN);
        const float4* Kr = (const float4*)(g_Km + row * NN);
        float4 w = Wr[t], kk = Kr[t];
        s += ur * (w.x * kk.x * vv.x + w.y * kk.y * vv.y
                 + w.z * kk.z * vv.z + w.w * kk.w * vv.w);
    }
    s = block_sum256(s);
    if (t == 0) g_partial[b] = s;
}

__global__ void loss_final_kernel(float* out) {
    int t = threadIdx.x;
    float s = block_sum256(g_partial[t]);
    if (t == 0) out[0] = LSCALE * s;
}

extern "C" void kernel_launch(void* const* d_in, const int* in_sizes, int n_in,
                              void* d_out, int out_size) {
    const float* ys = (const float*)d_in[0];
    const float* yt = (const float*)d_in[1];

    softmax_kernel<<<dim3(64, 2), 256>>>(ys, yt);
    wk_kernel<<<dim3(16, 16), 256>>>();
    init_kernel<<<4, 256>>>();
    for (int it = 0; it < NITERS; it++) {
        matvec_kernel<<<NN, 256>>>(0);
        matvec_kernel<<<NN, 256>>>(1);
    }
    loss_partial_kernel<<<256, 256>>>();
    loss_final_kernel<<<1, 256>>>((float*)d_out);
}